// round 5
// baseline (speedup 1.0000x reference)
#include <cuda_runtime.h>
#include <cstdint>

// ============================================================================
// Experts fused kernel via mma.sync tf32 (sm_103 base target — no tcgen05)
// Round 4: 512 threads / 16 warps, warp tile 32x32 -> 4 warps/SMSP for
// latency hiding (round 3 showed latency-bound, not issue-bound).
//   x  : [4,2048,512] f32  -> flat [8192,512]
//   w1 : [16,512,512] f32   == B for GEMM1 (row.col)
//   w2 : [16,512,128] f32   == B for GEMM2
//   out: [4,2048,128,16] f32, out[(tok*128 + d)*16 + e]
// ============================================================================

#define DEVINL __device__ __forceinline__

constexpr int NE   = 16;
constexpr int DIM  = 512;
constexpr int HID  = 512;
constexpr int DOUT = 128;
constexpr int TOK  = 8192;

constexpr int M     = 128;          // token tile
constexpr int NH    = 128;          // hidden chunk (GEMM1 N / GEMM2 K)
constexpr int KC    = 32;           // k-chunk for GEMM1 pipeline
constexpr int HC    = HID / NH;     // 4
constexpr int NKC   = DIM / KC;     // 16
constexpr int NT    = 512;          // threads per CTA

// tf32-pre-rounded copies of the inputs
__device__ float g_xr [TOK * DIM];
__device__ float g_w1r[NE * DIM * HID];
__device__ float g_w2r[NE * HID * DOUT];

// SMEM layout in floats
constexpr int LDX  = 36;            // Xs row stride  (bank-free A frags)
constexpr int LDW  = 132;           // W1s/W2s/Hs row stride (bank-free B/A frags)
constexpr int XS0  = 0;
constexpr int XS1  = XS0 + M * LDX;
constexpr int W1S0 = XS1 + M * LDX;
constexpr int W1S1 = W1S0 + KC * LDW;
constexpr int HS   = W1S1 + KC * LDW;
constexpr int W2S  = HS + M * LDW;
constexpr int SMEM_FLOATS = W2S + NH * LDW;
constexpr int SMEM_BYTES  = SMEM_FLOATS * 4;   // 205824

// ---------------------------------------------------------------------------
DEVINL uint32_t smem_u32(const void* p) {
    uint32_t a;
    asm("{ .reg .u64 t; cvta.to.shared.u64 t, %1; cvt.u32.u64 %0, t; }"
        : "=r"(a) : "l"(p));
    return a;
}

DEVINL void cp16(uint32_t dst, const float* src) {
    asm volatile("cp.async.cg.shared.global [%0], [%1], 16;"
                 :: "r"(dst), "l"(src) : "memory");
}
DEVINL void cp_commit() { asm volatile("cp.async.commit_group;" ::: "memory"); }
template <int N>
DEVINL void cp_wait() { asm volatile("cp.async.wait_group %0;" :: "n"(N) : "memory"); }

DEVINL uint32_t f2tf(float f) {
    uint32_t r;
    asm("cvt.rna.tf32.f32 %0, %1;" : "=r"(r) : "f"(f));
    return r;
}

DEVINL void mma8(float* c, const uint32_t* a, const uint32_t* b) {
    asm volatile(
        "mma.sync.aligned.m16n8k8.row.col.f32.tf32.tf32.f32 "
        "{%0,%1,%2,%3}, {%4,%5,%6,%7}, {%8,%9}, {%0,%1,%2,%3};"
        : "+f"(c[0]), "+f"(c[1]), "+f"(c[2]), "+f"(c[3])
        : "r"(a[0]), "r"(a[1]), "r"(a[2]), "r"(a[3]), "r"(b[0]), "r"(b[1]));
}

DEVINL float gelu_exact(float v) {
    return 0.5f * v * (1.0f + erff(v * 0.70710678118654752f));
}

// ---------------------------------------------------------------------------
// prep: round fp32 -> tf32 bit pattern (float4)
// ---------------------------------------------------------------------------
__global__ void round_tf32_kernel(const float* __restrict__ src,
                                  float* __restrict__ dst, int n4) {
    int i = blockIdx.x * blockDim.x + threadIdx.x;
    if (i < n4) {
        float4 v = reinterpret_cast<const float4*>(src)[i];
        v.x = __uint_as_float(f2tf(v.x));
        v.y = __uint_as_float(f2tf(v.y));
        v.z = __uint_as_float(f2tf(v.z));
        v.w = __uint_as_float(f2tf(v.w));
        reinterpret_cast<float4*>(dst)[i] = v;
    }
}

// ---------------------------------------------------------------------------
// main fused kernel: grid (16 experts, 64 token tiles), 512 threads (16 warps)
// warp grid 4x4: warp tile 32 (M) x 32 (N)
// ---------------------------------------------------------------------------
__global__ void __launch_bounds__(NT, 1)
experts_fused_kernel(float* __restrict__ out) {
    extern __shared__ __align__(16) float smf[];
    const uint32_t sb = smem_u32(smf);

    const int tid = threadIdx.x;
    const int wid = tid >> 5;
    const int lid = tid & 31;
    const int wr  = wid >> 2;        // 0..3  (M dir)
    const int wc  = wid & 3;         // 0..3  (N dir)
    const int tq  = lid >> 2;        // 0..7  groupID
    const int tr  = lid & 3;         // 0..3  threadID_in_group

    const int e    = blockIdx.x;
    const int tile = blockIdx.y;

    const float* xt  = g_xr  + (size_t)tile * M * DIM;
    const float* w1e = g_w1r + (size_t)e * DIM * HID;
    const float* w2e = g_w2r + (size_t)e * HID * DOUT;

    float c2[2][4][4];
#pragma unroll
    for (int mi = 0; mi < 2; mi++)
#pragma unroll
        for (int ni = 0; ni < 4; ni++)
#pragma unroll
            for (int j = 0; j < 4; j++) c2[mi][ni][j] = 0.f;

    // cp.async copy helpers (512 threads) ------------------------------------
    auto copy_x_chunk = [&](int buf, int kc) {
        uint32_t base = sb + (buf ? XS1 : XS0) * 4;
#pragma unroll
        for (int i = 0; i < 2; i++) {
            int idx = tid + i * NT;           // 0..1023
            int row = idx >> 3;
            int v   = idx & 7;
            cp16(base + (row * LDX + v * 4) * 4,
                 xt + (size_t)row * DIM + kc * KC + v * 4);
        }
    };
    auto copy_w1_chunk = [&](int buf, int hc, int kc) {
        uint32_t base = sb + (buf ? W1S1 : W1S0) * 4;
#pragma unroll
        for (int i = 0; i < 2; i++) {
            int idx = tid + i * NT;
            int row = idx >> 5;               // 0..31 (k)
            int v   = idx & 31;               // 0..31 (h/4)
            cp16(base + (row * LDW + v * 4) * 4,
                 w1e + (size_t)(kc * KC + row) * HID + hc * NH + v * 4);
        }
    };
    auto copy_w2_chunk = [&](int hc) {
        uint32_t base = sb + W2S * 4;
#pragma unroll
        for (int i = 0; i < 8; i++) {
            int idx = tid + i * NT;
            int row = idx >> 5;               // 0..127 (h)
            int v   = idx & 31;
            cp16(base + (row * LDW + v * 4) * 4,
                 w2e + (size_t)(hc * NH + row) * DOUT + v * 4);
        }
    };

    const float* Hsp  = smf + HS;
    const float* W2sp = smf + W2S;

    for (int hc = 0; hc < HC; hc++) {
        // prefetch W2 chunk + first k-chunk
        copy_w2_chunk(hc);
        cp_commit();
        copy_x_chunk(0, 0);
        copy_w1_chunk(0, hc, 0);
        cp_commit();

        float c1[2][4][4];
#pragma unroll
        for (int mi = 0; mi < 2; mi++)
#pragma unroll
            for (int ni = 0; ni < 4; ni++)
#pragma unroll
                for (int j = 0; j < 4; j++) c1[mi][ni][j] = 0.f;

        // ---- GEMM1: C1[128,128] = X[128,512] @ W1[:, hc*128..] ----
        for (int kc = 0; kc < NKC; kc++) {
            if (kc + 1 < NKC) {
                copy_x_chunk((kc + 1) & 1, kc + 1);
                copy_w1_chunk((kc + 1) & 1, hc, kc + 1);
                cp_commit();
                cp_wait<1>();
            } else {
                cp_wait<0>();
            }
            __syncthreads();

            const float* Xb = smf + ((kc & 1) ? XS1 : XS0);
            const float* Wb = smf + ((kc & 1) ? W1S1 : W1S0);
#pragma unroll
            for (int ks = 0; ks < 4; ks++) {
                const int k0 = ks * 8;
                uint32_t a[2][4], b[4][2];
#pragma unroll
                for (int mi = 0; mi < 2; mi++) {
                    const int m0 = wr * 32 + mi * 16;
                    a[mi][0] = __float_as_uint(Xb[(m0 + tq) * LDX + k0 + tr]);
                    a[mi][1] = __float_as_uint(Xb[(m0 + tq + 8) * LDX + k0 + tr]);
                    a[mi][2] = __float_as_uint(Xb[(m0 + tq) * LDX + k0 + tr + 4]);
                    a[mi][3] = __float_as_uint(Xb[(m0 + tq + 8) * LDX + k0 + tr + 4]);
                }
#pragma unroll
                for (int ni = 0; ni < 4; ni++) {
                    const int n0 = wc * 32 + ni * 8;
                    b[ni][0] = __float_as_uint(Wb[(k0 + tr) * LDW + n0 + tq]);
                    b[ni][1] = __float_as_uint(Wb[(k0 + tr + 4) * LDW + n0 + tq]);
                }
#pragma unroll
                for (int mi = 0; mi < 2; mi++)
#pragma unroll
                    for (int ni = 0; ni < 4; ni++)
                        mma8(c1[mi][ni], a[mi], b[ni]);
            }
            __syncthreads();
        }

        // ---- GELU -> Hs (tf32-rounded at store) ----
        {
            float* Hw = smf + HS;
#pragma unroll
            for (int mi = 0; mi < 2; mi++) {
                const int m0 = wr * 32 + mi * 16;
#pragma unroll
                for (int ni = 0; ni < 4; ni++) {
                    const int n0 = wc * 32 + ni * 8;
                    const int col = n0 + 2 * tr;
                    Hw[(m0 + tq) * LDW + col] =
                        __uint_as_float(f2tf(gelu_exact(c1[mi][ni][0])));
                    Hw[(m0 + tq) * LDW + col + 1] =
                        __uint_as_float(f2tf(gelu_exact(c1[mi][ni][1])));
                    Hw[(m0 + tq + 8) * LDW + col] =
                        __uint_as_float(f2tf(gelu_exact(c1[mi][ni][2])));
                    Hw[(m0 + tq + 8) * LDW + col + 1] =
                        __uint_as_float(f2tf(gelu_exact(c1[mi][ni][3])));
                }
            }
        }
        __syncthreads();

        // ---- GEMM2: C2 += Hs[128,128] @ W2chunk[128,128] ----
#pragma unroll
        for (int ks = 0; ks < 16; ks++) {
            const int k0 = ks * 8;
            uint32_t a[2][4], b[4][2];
#pragma unroll
            for (int mi = 0; mi < 2; mi++) {
                const int m0 = wr * 32 + mi * 16;
                a[mi][0] = __float_as_uint(Hsp[(m0 + tq) * LDW + k0 + tr]);
                a[mi][1] = __float_as_uint(Hsp[(m0 + tq + 8) * LDW + k0 + tr]);
                a[mi][2] = __float_as_uint(Hsp[(m0 + tq) * LDW + k0 + tr + 4]);
                a[mi][3] = __float_as_uint(Hsp[(m0 + tq + 8) * LDW + k0 + tr + 4]);
            }
#pragma unroll
            for (int ni = 0; ni < 4; ni++) {
                const int n0 = wc * 32 + ni * 8;
                b[ni][0] = __float_as_uint(W2sp[(k0 + tr) * LDW + n0 + tq]);
                b[ni][1] = __float_as_uint(W2sp[(k0 + tr + 4) * LDW + n0 + tq]);
            }
#pragma unroll
            for (int mi = 0; mi < 2; mi++)
#pragma unroll
                for (int ni = 0; ni < 4; ni++)
                    mma8(c2[mi][ni], a[mi], b[ni]);
        }
        __syncthreads();
    }

    // ---- epilogue: scatter C2 -> out[(tok*128 + d)*16 + e] ----
#pragma unroll
    for (int mi = 0; mi < 2; mi++) {
        const size_t tok0 = (size_t)tile * M + wr * 32 + mi * 16 + tq;
#pragma unroll
        for (int ni = 0; ni < 4; ni++) {
            const int d0 = wc * 32 + ni * 8 + 2 * tr;
            out[(tok0 * DOUT + d0) * NE + e]           = c2[mi][ni][0];
            out[(tok0 * DOUT + d0 + 1) * NE + e]       = c2[mi][ni][1];
            out[((tok0 + 8) * DOUT + d0) * NE + e]     = c2[mi][ni][2];
            out[((tok0 + 8) * DOUT + d0 + 1) * NE + e] = c2[mi][ni][3];
        }
    }
}

// ---------------------------------------------------------------------------
extern "C" void kernel_launch(void* const* d_in, const int* in_sizes, int n_in,
                              void* d_out, int out_size) {
    const float* x  = (const float*)d_in[0];
    const float* w1 = (const float*)d_in[1];
    const float* w2 = (const float*)d_in[2];
    float* out      = (float*)d_out;

    float* xr;  cudaGetSymbolAddress((void**)&xr,  g_xr);
    float* w1r; cudaGetSymbolAddress((void**)&w1r, g_w1r);
    float* w2r; cudaGetSymbolAddress((void**)&w2r, g_w2r);

    constexpr int NX  = TOK * DIM / 4;
    constexpr int NW1 = NE * DIM * HID / 4;
    constexpr int NW2 = NE * HID * DOUT / 4;
    round_tf32_kernel<<<(NX  + 255) / 256, 256>>>(x,  xr,  NX);
    round_tf32_kernel<<<(NW1 + 255) / 256, 256>>>(w1, w1r, NW1);
    round_tf32_kernel<<<(NW2 + 255) / 256, 256>>>(w2, w2r, NW2);

    cudaFuncSetAttribute(experts_fused_kernel,
                         cudaFuncAttributeMaxDynamicSharedMemorySize, SMEM_BYTES);

    experts_fused_kernel<<<dim3(NE, TOK / M), NT, SMEM_BYTES>>>(out);
}

// round 6
// speedup vs baseline: 1.2283x; 1.2283x over previous
#include <cuda_runtime.h>
#include <cstdint>

// ============================================================================
// Experts fused kernel via mma.sync tf32 (sm_103 base target — no tcgen05)
// Round 5: fix 4-way bank conflict on B-fragment loads.
//   A-pattern arrays (Xs, Hs): stride ≡ 4 (mod 32)  -> bank = 4*tq+tr ✓
//   B-pattern arrays (W1s, W2s): stride ≡ 8 (mod 32) -> bank = 8*tr+tq ✓
//   x  : [4,2048,512] f32  -> flat [8192,512]
//   w1 : [16,512,512] f32   == B for GEMM1 (row.col)
//   w2 : [16,512,128] f32   == B for GEMM2
//   out: [4,2048,128,16] f32, out[(tok*128 + d)*16 + e]
// ============================================================================

#define DEVINL __device__ __forceinline__

constexpr int NE   = 16;
constexpr int DIM  = 512;
constexpr int HID  = 512;
constexpr int DOUT = 128;
constexpr int TOK  = 8192;

constexpr int M     = 128;          // token tile
constexpr int NH    = 128;          // hidden chunk (GEMM1 N / GEMM2 K)
constexpr int KC    = 32;           // k-chunk for GEMM1 pipeline
constexpr int HC    = HID / NH;     // 4
constexpr int NKC   = DIM / KC;     // 16

// tf32-pre-rounded copies of the inputs
__device__ float g_xr [TOK * DIM];
__device__ float g_w1r[NE * DIM * HID];
__device__ float g_w2r[NE * HID * DOUT];

// SMEM layout in floats
constexpr int LDX  = 36;            // Xs row stride   (A-frag: bank=4tq+tr, free)
constexpr int LDW  = 132;           // Hs row stride   (A-frag in GEMM2, free)
constexpr int LDB  = 136;           // W1s/W2s stride  (B-frag: bank=8tr+tq, free)
constexpr int XS0  = 0;
constexpr int XS1  = XS0 + M * LDX;          // 4608
constexpr int W1S0 = XS1 + M * LDX;          // 9216
constexpr int W1S1 = W1S0 + KC * LDB;        // 13568
constexpr int HS   = W1S1 + KC * LDB;        // 17920
constexpr int W2S  = HS + M * LDW;           // 34816
constexpr int SMEM_FLOATS = W2S + NH * LDB;  // 52224
constexpr int SMEM_BYTES  = SMEM_FLOATS * 4; // 208896

// ---------------------------------------------------------------------------
DEVINL uint32_t smem_u32(const void* p) {
    uint32_t a;
    asm("{ .reg .u64 t; cvta.to.shared.u64 t, %1; cvt.u32.u64 %0, t; }"
        : "=r"(a) : "l"(p));
    return a;
}

DEVINL void cp16(uint32_t dst, const float* src) {
    asm volatile("cp.async.cg.shared.global [%0], [%1], 16;"
                 :: "r"(dst), "l"(src) : "memory");
}
DEVINL void cp_commit() { asm volatile("cp.async.commit_group;" ::: "memory"); }
template <int N>
DEVINL void cp_wait() { asm volatile("cp.async.wait_group %0;" :: "n"(N) : "memory"); }

DEVINL uint32_t f2tf(float f) {
    uint32_t r;
    asm("cvt.rna.tf32.f32 %0, %1;" : "=r"(r) : "f"(f));
    return r;
}

DEVINL void mma8(float* c, const uint32_t* a, const uint32_t* b) {
    asm volatile(
        "mma.sync.aligned.m16n8k8.row.col.f32.tf32.tf32.f32 "
        "{%0,%1,%2,%3}, {%4,%5,%6,%7}, {%8,%9}, {%0,%1,%2,%3};"
        : "+f"(c[0]), "+f"(c[1]), "+f"(c[2]), "+f"(c[3])
        : "r"(a[0]), "r"(a[1]), "r"(a[2]), "r"(a[3]), "r"(b[0]), "r"(b[1]));
}

DEVINL float gelu_exact(float v) {
    return 0.5f * v * (1.0f + erff(v * 0.70710678118654752f));
}

// ---------------------------------------------------------------------------
// prep: round fp32 -> tf32 bit pattern (float4)
// ---------------------------------------------------------------------------
__global__ void round_tf32_kernel(const float* __restrict__ src,
                                  float* __restrict__ dst, int n4) {
    int i = blockIdx.x * blockDim.x + threadIdx.x;
    if (i < n4) {
        float4 v = reinterpret_cast<const float4*>(src)[i];
        v.x = __uint_as_float(f2tf(v.x));
        v.y = __uint_as_float(f2tf(v.y));
        v.z = __uint_as_float(f2tf(v.z));
        v.w = __uint_as_float(f2tf(v.w));
        reinterpret_cast<float4*>(dst)[i] = v;
    }
}

// ---------------------------------------------------------------------------
// main fused kernel: grid (16 experts, 64 token tiles), 256 threads (8 warps)
// warp grid 4x2: warp tile 32 (M) x 64 (N)
// ---------------------------------------------------------------------------
__global__ void __launch_bounds__(256, 1)
experts_fused_kernel(float* __restrict__ out) {
    extern __shared__ __align__(16) float smf[];
    const uint32_t sb = smem_u32(smf);

    const int tid = threadIdx.x;
    const int wid = tid >> 5;
    const int lid = tid & 31;
    const int wr  = wid >> 1;        // 0..3  (M dir)
    const int wc  = wid & 1;         // 0..1  (N dir)
    const int tq  = lid >> 2;        // 0..7  groupID
    const int tr  = lid & 3;         // 0..3  threadID_in_group

    const int e    = blockIdx.x;
    const int tile = blockIdx.y;

    const float* xt  = g_xr  + (size_t)tile * M * DIM;
    const float* w1e = g_w1r + (size_t)e * DIM * HID;
    const float* w2e = g_w2r + (size_t)e * HID * DOUT;

    float c2[2][8][4];
#pragma unroll
    for (int mi = 0; mi < 2; mi++)
#pragma unroll
        for (int ni = 0; ni < 8; ni++)
#pragma unroll
            for (int j = 0; j < 4; j++) c2[mi][ni][j] = 0.f;

    // cp.async copy helpers -------------------------------------------------
    auto copy_x_chunk = [&](int buf, int kc) {
        uint32_t base = sb + (buf ? XS1 : XS0) * 4;
#pragma unroll
        for (int i = 0; i < 4; i++) {
            int idx = tid + i * 256;          // 0..1023
            int row = idx >> 3;
            int v   = idx & 7;
            cp16(base + (row * LDX + v * 4) * 4,
                 xt + (size_t)row * DIM + kc * KC + v * 4);
        }
    };
    auto copy_w1_chunk = [&](int buf, int hc, int kc) {
        uint32_t base = sb + (buf ? W1S1 : W1S0) * 4;
#pragma unroll
        for (int i = 0; i < 4; i++) {
            int idx = tid + i * 256;
            int row = idx >> 5;               // 0..31 (k)
            int v   = idx & 31;               // 0..31 (h/4)
            cp16(base + (row * LDB + v * 4) * 4,
                 w1e + (size_t)(kc * KC + row) * HID + hc * NH + v * 4);
        }
    };
    auto copy_w2_chunk = [&](int hc) {
        uint32_t base = sb + W2S * 4;
#pragma unroll
        for (int i = 0; i < 16; i++) {
            int idx = tid + i * 256;
            int row = idx >> 5;               // 0..127 (h)
            int v   = idx & 31;
            cp16(base + (row * LDB + v * 4) * 4,
                 w2e + (size_t)(hc * NH + row) * DOUT + v * 4);
        }
    };

    const float* Hsp  = smf + HS;
    const float* W2sp = smf + W2S;

    for (int hc = 0; hc < HC; hc++) {
        // prefetch W2 chunk + first k-chunk
        copy_w2_chunk(hc);
        cp_commit();
        copy_x_chunk(0, 0);
        copy_w1_chunk(0, hc, 0);
        cp_commit();

        float c1[2][8][4];
#pragma unroll
        for (int mi = 0; mi < 2; mi++)
#pragma unroll
            for (int ni = 0; ni < 8; ni++)
#pragma unroll
                for (int j = 0; j < 4; j++) c1[mi][ni][j] = 0.f;

        // ---- GEMM1: C1[128,128] = X[128,512] @ W1[:, hc*128..] ----
        for (int kc = 0; kc < NKC; kc++) {
            if (kc + 1 < NKC) {
                copy_x_chunk((kc + 1) & 1, kc + 1);
                copy_w1_chunk((kc + 1) & 1, hc, kc + 1);
                cp_commit();
                cp_wait<1>();
            } else {
                cp_wait<0>();
            }
            __syncthreads();

            const float* Xb = smf + ((kc & 1) ? XS1 : XS0);
            const float* Wb = smf + ((kc & 1) ? W1S1 : W1S0);
#pragma unroll
            for (int ks = 0; ks < 4; ks++) {
                const int k0 = ks * 8;
                uint32_t a[2][4], b[8][2];
#pragma unroll
                for (int mi = 0; mi < 2; mi++) {
                    const int m0 = wr * 32 + mi * 16;
                    a[mi][0] = __float_as_uint(Xb[(m0 + tq) * LDX + k0 + tr]);
                    a[mi][1] = __float_as_uint(Xb[(m0 + tq + 8) * LDX + k0 + tr]);
                    a[mi][2] = __float_as_uint(Xb[(m0 + tq) * LDX + k0 + tr + 4]);
                    a[mi][3] = __float_as_uint(Xb[(m0 + tq + 8) * LDX + k0 + tr + 4]);
                }
#pragma unroll
                for (int ni = 0; ni < 8; ni++) {
                    const int n0 = wc * 64 + ni * 8;
                    b[ni][0] = __float_as_uint(Wb[(k0 + tr) * LDB + n0 + tq]);
                    b[ni][1] = __float_as_uint(Wb[(k0 + tr + 4) * LDB + n0 + tq]);
                }
#pragma unroll
                for (int mi = 0; mi < 2; mi++)
#pragma unroll
                    for (int ni = 0; ni < 8; ni++)
                        mma8(c1[mi][ni], a[mi], b[ni]);
            }
            __syncthreads();
        }

        // ---- GELU -> Hs (tf32-rounded at store) ----
        {
            float* Hw = smf + HS;
#pragma unroll
            for (int mi = 0; mi < 2; mi++) {
                const int m0 = wr * 32 + mi * 16;
#pragma unroll
                for (int ni = 0; ni < 8; ni++) {
                    const int n0 = wc * 64 + ni * 8;
                    const int col = n0 + 2 * tr;
                    Hw[(m0 + tq) * LDW + col] =
                        __uint_as_float(f2tf(gelu_exact(c1[mi][ni][0])));
                    Hw[(m0 + tq) * LDW + col + 1] =
                        __uint_as_float(f2tf(gelu_exact(c1[mi][ni][1])));
                    Hw[(m0 + tq + 8) * LDW + col] =
                        __uint_as_float(f2tf(gelu_exact(c1[mi][ni][2])));
                    Hw[(m0 + tq + 8) * LDW + col + 1] =
                        __uint_as_float(f2tf(gelu_exact(c1[mi][ni][3])));
                }
            }
        }
        __syncthreads();

        // ---- GEMM2: C2 += Hs[128,128] @ W2chunk[128,128] ----
#pragma unroll
        for (int ks = 0; ks < 16; ks++) {
            const int k0 = ks * 8;
            uint32_t a[2][4], b[8][2];
#pragma unroll
            for (int mi = 0; mi < 2; mi++) {
                const int m0 = wr * 32 + mi * 16;
                a[mi][0] = __float_as_uint(Hsp[(m0 + tq) * LDW + k0 + tr]);
                a[mi][1] = __float_as_uint(Hsp[(m0 + tq + 8) * LDW + k0 + tr]);
                a[mi][2] = __float_as_uint(Hsp[(m0 + tq) * LDW + k0 + tr + 4]);
                a[mi][3] = __float_as_uint(Hsp[(m0 + tq + 8) * LDW + k0 + tr + 4]);
            }
#pragma unroll
            for (int ni = 0; ni < 8; ni++) {
                const int n0 = wc * 64 + ni * 8;
                b[ni][0] = __float_as_uint(W2sp[(k0 + tr) * LDB + n0 + tq]);
                b[ni][1] = __float_as_uint(W2sp[(k0 + tr + 4) * LDB + n0 + tq]);
            }
#pragma unroll
            for (int mi = 0; mi < 2; mi++)
#pragma unroll
                for (int ni = 0; ni < 8; ni++)
                    mma8(c2[mi][ni], a[mi], b[ni]);
        }
        __syncthreads();
    }

    // ---- epilogue: scatter C2 -> out[(tok*128 + d)*16 + e] ----
#pragma unroll
    for (int mi = 0; mi < 2; mi++) {
        const size_t tok0 = (size_t)tile * M + wr * 32 + mi * 16 + tq;
#pragma unroll
        for (int ni = 0; ni < 8; ni++) {
            const int d0 = wc * 64 + ni * 8 + 2 * tr;
            out[(tok0 * DOUT + d0) * NE + e]           = c2[mi][ni][0];
            out[(tok0 * DOUT + d0 + 1) * NE + e]       = c2[mi][ni][1];
            out[((tok0 + 8) * DOUT + d0) * NE + e]     = c2[mi][ni][2];
            out[((tok0 + 8) * DOUT + d0 + 1) * NE + e] = c2[mi][ni][3];
        }
    }
}

// ---------------------------------------------------------------------------
extern "C" void kernel_launch(void* const* d_in, const int* in_sizes, int n_in,
                              void* d_out, int out_size) {
    const float* x  = (const float*)d_in[0];
    const float* w1 = (const float*)d_in[1];
    const float* w2 = (const float*)d_in[2];
    float* out      = (float*)d_out;

    float* xr;  cudaGetSymbolAddress((void**)&xr,  g_xr);
    float* w1r; cudaGetSymbolAddress((void**)&w1r, g_w1r);
    float* w2r; cudaGetSymbolAddress((void**)&w2r, g_w2r);

    constexpr int NX  = TOK * DIM / 4;
    constexpr int NW1 = NE * DIM * HID / 4;
    constexpr int NW2 = NE * HID * DOUT / 4;
    round_tf32_kernel<<<(NX  + 255) / 256, 256>>>(x,  xr,  NX);
    round_tf32_kernel<<<(NW1 + 255) / 256, 256>>>(w1, w1r, NW1);
    round_tf32_kernel<<<(NW2 + 255) / 256, 256>>>(w2, w2r, NW2);

    cudaFuncSetAttribute(experts_fused_kernel,
                         cudaFuncAttributeMaxDynamicSharedMemorySize, SMEM_BYTES);

    experts_fused_kernel<<<dim3(NE, TOK / M), 256, SMEM_BYTES>>>(out);
}

// round 7
// speedup vs baseline: 1.3451x; 1.0951x over previous
#include <cuda_runtime.h>
#include <cstdint>

// ============================================================================
// Experts — two-stage GEMM via mma.sync tf32 (sm_103 base target)
// Round 6: split fused kernel into GEMM1+GELU and GEMM2 so each runs at
// 2 CTAs/SM (4 warps/SMSP) for latency hiding. H staged in 256MB scratch.
//   x  : [4,2048,512] f32  -> flat [8192,512]
//   w1 : [16,512,512] f32   == B for GEMM1 (row.col)
//   w2 : [16,512,128] f32   == B for GEMM2
//   out: [4,2048,128,16] f32, out[(tok*128 + d)*16 + e]
// ============================================================================

#define DEVINL __device__ __forceinline__

constexpr int NE   = 16;
constexpr int DIM  = 512;
constexpr int HID  = 512;
constexpr int DOUT = 128;
constexpr int TOK  = 8192;

constexpr int M   = 128;            // token tile
constexpr int KC  = 32;             // k-chunk
constexpr int NKC = DIM / KC;       // 16

// tf32-pre-rounded inputs + hidden scratch
__device__ float g_xr [TOK * DIM];
__device__ float g_w1r[NE * DIM * HID];
__device__ float g_w2r[NE * HID * DOUT];
__device__ float g_h  [(size_t)NE * TOK * HID];   // 256 MB

// SMEM layout in floats (identical for both GEMM kernels)
constexpr int LDX  = 36;            // A tile row stride (bank = 4tq+tr, free)
constexpr int LDB  = 136;           // B tile row stride (bank = 8tr+tq, free)
constexpr int AS0  = 0;
constexpr int AS1  = AS0 + M * LDX;          // 4608
constexpr int BS0  = AS1 + M * LDX;          // 9216
constexpr int BS1  = BS0 + KC * LDB;         // 13568
constexpr int SMEM_FLOATS = BS1 + KC * LDB;  // 17920
constexpr int SMEM_BYTES  = SMEM_FLOATS * 4; // 71680

// ---------------------------------------------------------------------------
DEVINL uint32_t smem_u32(const void* p) {
    uint32_t a;
    asm("{ .reg .u64 t; cvta.to.shared.u64 t, %1; cvt.u32.u64 %0, t; }"
        : "=r"(a) : "l"(p));
    return a;
}

DEVINL void cp16(uint32_t dst, const float* src) {
    asm volatile("cp.async.cg.shared.global [%0], [%1], 16;"
                 :: "r"(dst), "l"(src) : "memory");
}
DEVINL void cp_commit() { asm volatile("cp.async.commit_group;" ::: "memory"); }
template <int N>
DEVINL void cp_wait() { asm volatile("cp.async.wait_group %0;" :: "n"(N) : "memory"); }

DEVINL uint32_t f2tf(float f) {
    uint32_t r;
    asm("cvt.rna.tf32.f32 %0, %1;" : "=r"(r) : "f"(f));
    return r;
}

DEVINL void mma8(float* c, const uint32_t* a, const uint32_t* b) {
    asm volatile(
        "mma.sync.aligned.m16n8k8.row.col.f32.tf32.tf32.f32 "
        "{%0,%1,%2,%3}, {%4,%5,%6,%7}, {%8,%9}, {%0,%1,%2,%3};"
        : "+f"(c[0]), "+f"(c[1]), "+f"(c[2]), "+f"(c[3])
        : "r"(a[0]), "r"(a[1]), "r"(a[2]), "r"(a[3]), "r"(b[0]), "r"(b[1]));
}

DEVINL float gelu_exact(float v) {
    return 0.5f * v * (1.0f + erff(v * 0.70710678118654752f));
}

// ---------------------------------------------------------------------------
// prep: round fp32 -> tf32 bit pattern (float4)
// ---------------------------------------------------------------------------
__global__ void round_tf32_kernel(const float* __restrict__ src,
                                  float* __restrict__ dst, int n4) {
    int i = blockIdx.x * blockDim.x + threadIdx.x;
    if (i < n4) {
        float4 v = reinterpret_cast<const float4*>(src)[i];
        v.x = __uint_as_float(f2tf(v.x));
        v.y = __uint_as_float(f2tf(v.y));
        v.z = __uint_as_float(f2tf(v.z));
        v.w = __uint_as_float(f2tf(v.w));
        reinterpret_cast<float4*>(dst)[i] = v;
    }
}

// ---------------------------------------------------------------------------
// shared copy helpers: A tile is [128 tok-rows x 32 k], B tile is [32 k x 128 n]
// ---------------------------------------------------------------------------
DEVINL void copy_a_chunk(uint32_t sbase, int tid, const float* __restrict__ src,
                         int ld) {
#pragma unroll
    for (int i = 0; i < 4; i++) {
        int idx = tid + i * 256;              // 0..1023
        int row = idx >> 3;                   // 0..127
        int v   = idx & 7;                    // float4 col
        cp16(sbase + (uint32_t)(row * LDX + v * 4) * 4,
             src + (size_t)row * ld + v * 4);
    }
}
DEVINL void copy_b_chunk(uint32_t sbase, int tid, const float* __restrict__ src,
                         int ld) {
#pragma unroll
    for (int i = 0; i < 4; i++) {
        int idx = tid + i * 256;
        int row = idx >> 5;                   // 0..31 (k)
        int v   = idx & 31;                   // float4 col (n/4)
        cp16(sbase + (uint32_t)(row * LDB + v * 4) * 4,
             src + (size_t)row * ld + v * 4);
    }
}

// ---------------------------------------------------------------------------
// generic 128x128xK512 tf32 mainloop body (A row-major, B row.col)
// c[2][8][4] accumulators; 8 warps 4x2, warp tile 32x64.
// ---------------------------------------------------------------------------
DEVINL void gemm_mainloop(const float* __restrict__ a_g, int lda,
                          const float* __restrict__ b_g, int ldb,
                          float* smf, uint32_t sb, int tid,
                          int wr, int wc, int tq, int tr,
                          float c[2][8][4]) {
    copy_a_chunk(sb + AS0 * 4, tid, a_g, lda);
    copy_b_chunk(sb + BS0 * 4, tid, b_g, ldb);
    cp_commit();

    for (int kc = 0; kc < NKC; kc++) {
        if (kc + 1 < NKC) {
            uint32_t ab = sb + (((kc + 1) & 1) ? AS1 : AS0) * 4;
            uint32_t bb = sb + (((kc + 1) & 1) ? BS1 : BS0) * 4;
            copy_a_chunk(ab, tid, a_g + (kc + 1) * KC, lda);
            copy_b_chunk(bb, tid, b_g + (size_t)(kc + 1) * KC * ldb, ldb);
            cp_commit();
            cp_wait<1>();
        } else {
            cp_wait<0>();
        }
        __syncthreads();

        const float* Ab = smf + ((kc & 1) ? AS1 : AS0);
        const float* Bb = smf + ((kc & 1) ? BS1 : BS0);
#pragma unroll
        for (int ks = 0; ks < 4; ks++) {
            const int k0 = ks * 8;
            uint32_t a[2][4], b[8][2];
#pragma unroll
            for (int mi = 0; mi < 2; mi++) {
                const int m0 = wr * 32 + mi * 16;
                a[mi][0] = __float_as_uint(Ab[(m0 + tq) * LDX + k0 + tr]);
                a[mi][1] = __float_as_uint(Ab[(m0 + tq + 8) * LDX + k0 + tr]);
                a[mi][2] = __float_as_uint(Ab[(m0 + tq) * LDX + k0 + tr + 4]);
                a[mi][3] = __float_as_uint(Ab[(m0 + tq + 8) * LDX + k0 + tr + 4]);
            }
#pragma unroll
            for (int ni = 0; ni < 8; ni++) {
                const int n0 = wc * 64 + ni * 8;
                b[ni][0] = __float_as_uint(Bb[(k0 + tr) * LDB + n0 + tq]);
                b[ni][1] = __float_as_uint(Bb[(k0 + tr + 4) * LDB + n0 + tq]);
            }
#pragma unroll
            for (int mi = 0; mi < 2; mi++)
#pragma unroll
                for (int ni = 0; ni < 8; ni++)
                    mma8(c[mi][ni], a[mi], b[ni]);
        }
        __syncthreads();
    }
}

// ---------------------------------------------------------------------------
// Kernel A: H[e][tok][h] = tf32(gelu(X @ W1[e]))   grid (64 n/e combos, 64 tiles)
// ---------------------------------------------------------------------------
__global__ void __launch_bounds__(256, 2)
gemm1_gelu_kernel() {
    extern __shared__ __align__(16) float smf[];
    const uint32_t sb = smem_u32(smf);

    const int tid = threadIdx.x;
    const int wid = tid >> 5, lid = tid & 31;
    const int wr = wid >> 1, wc = wid & 1;
    const int tq = lid >> 2, tr = lid & 3;

    const int e    = blockIdx.x & (NE - 1);
    const int nt   = blockIdx.x >> 4;        // 0..3 hidden 128-col tile
    const int tile = blockIdx.y;

    const float* a_g = g_xr  + (size_t)tile * M * DIM;
    const float* b_g = g_w1r + (size_t)e * DIM * HID + nt * 128;

    float c[2][8][4];
#pragma unroll
    for (int mi = 0; mi < 2; mi++)
#pragma unroll
        for (int ni = 0; ni < 8; ni++)
#pragma unroll
            for (int j = 0; j < 4; j++) c[mi][ni][j] = 0.f;

    gemm_mainloop(a_g, DIM, b_g, HID, smf, sb, tid, wr, wc, tq, tr, c);

    // epilogue: gelu + tf32-round + store to H (h contiguous)
    float* hg = g_h + ((size_t)e * TOK + (size_t)tile * M) * HID + nt * 128;
#pragma unroll
    for (int mi = 0; mi < 2; mi++) {
        const int m0 = wr * 32 + mi * 16;
#pragma unroll
        for (int ni = 0; ni < 8; ni++) {
            const int n0 = wc * 64 + ni * 8 + 2 * tr;
            float2 v0, v1;
            v0.x = __uint_as_float(f2tf(gelu_exact(c[mi][ni][0])));
            v0.y = __uint_as_float(f2tf(gelu_exact(c[mi][ni][1])));
            v1.x = __uint_as_float(f2tf(gelu_exact(c[mi][ni][2])));
            v1.y = __uint_as_float(f2tf(gelu_exact(c[mi][ni][3])));
            *reinterpret_cast<float2*>(hg + (size_t)(m0 + tq) * HID + n0)     = v0;
            *reinterpret_cast<float2*>(hg + (size_t)(m0 + tq + 8) * HID + n0) = v1;
        }
    }
}

// ---------------------------------------------------------------------------
// Kernel B: out = H[e] @ W2[e]   grid (16 experts, 64 tiles)
// ---------------------------------------------------------------------------
__global__ void __launch_bounds__(256, 2)
gemm2_kernel(float* __restrict__ out) {
    extern __shared__ __align__(16) float smf[];
    const uint32_t sb = smem_u32(smf);

    const int tid = threadIdx.x;
    const int wid = tid >> 5, lid = tid & 31;
    const int wr = wid >> 1, wc = wid & 1;
    const int tq = lid >> 2, tr = lid & 3;

    const int e    = blockIdx.x;
    const int tile = blockIdx.y;

    const float* a_g = g_h   + ((size_t)e * TOK + (size_t)tile * M) * HID;
    const float* b_g = g_w2r + (size_t)e * HID * DOUT;

    float c[2][8][4];
#pragma unroll
    for (int mi = 0; mi < 2; mi++)
#pragma unroll
        for (int ni = 0; ni < 8; ni++)
#pragma unroll
            for (int j = 0; j < 4; j++) c[mi][ni][j] = 0.f;

    gemm_mainloop(a_g, HID, b_g, DOUT, smf, sb, tid, wr, wc, tq, tr, c);

    // epilogue: scatter to out[(tok*128 + d)*16 + e]
#pragma unroll
    for (int mi = 0; mi < 2; mi++) {
        const size_t tok0 = (size_t)tile * M + wr * 32 + mi * 16 + tq;
#pragma unroll
        for (int ni = 0; ni < 8; ni++) {
            const int d0 = wc * 64 + ni * 8 + 2 * tr;
            out[(tok0 * DOUT + d0) * NE + e]           = c[mi][ni][0];
            out[(tok0 * DOUT + d0 + 1) * NE + e]       = c[mi][ni][1];
            out[((tok0 + 8) * DOUT + d0) * NE + e]     = c[mi][ni][2];
            out[((tok0 + 8) * DOUT + d0 + 1) * NE + e] = c[mi][ni][3];
        }
    }
}

// ---------------------------------------------------------------------------
extern "C" void kernel_launch(void* const* d_in, const int* in_sizes, int n_in,
                              void* d_out, int out_size) {
    const float* x  = (const float*)d_in[0];
    const float* w1 = (const float*)d_in[1];
    const float* w2 = (const float*)d_in[2];
    float* out      = (float*)d_out;

    float* xr;  cudaGetSymbolAddress((void**)&xr,  g_xr);
    float* w1r; cudaGetSymbolAddress((void**)&w1r, g_w1r);
    float* w2r; cudaGetSymbolAddress((void**)&w2r, g_w2r);

    constexpr int NX  = TOK * DIM / 4;
    constexpr int NW1 = NE * DIM * HID / 4;
    constexpr int NW2 = NE * HID * DOUT / 4;
    round_tf32_kernel<<<(NX  + 255) / 256, 256>>>(x,  xr,  NX);
    round_tf32_kernel<<<(NW1 + 255) / 256, 256>>>(w1, w1r, NW1);
    round_tf32_kernel<<<(NW2 + 255) / 256, 256>>>(w2, w2r, NW2);

    cudaFuncSetAttribute(gemm1_gelu_kernel,
                         cudaFuncAttributeMaxDynamicSharedMemorySize, SMEM_BYTES);
    cudaFuncSetAttribute(gemm2_kernel,
                         cudaFuncAttributeMaxDynamicSharedMemorySize, SMEM_BYTES);

    gemm1_gelu_kernel<<<dim3(NE * (HID / 128), TOK / M), 256, SMEM_BYTES>>>();
    gemm2_kernel<<<dim3(NE, TOK / M), 256, SMEM_BYTES>>>(out);
}